// round 6
// baseline (speedup 1.0000x reference)
#include <cuda_runtime.h>
#include <cuda_bf16.h>

#define EPS   1e-6f
#define NCOLS 4096
#define MAXB  8192

// Per-row partials + completion counter (no device allocation; graph-replay safe).
__device__ float g_pw[MAXB];       // sum over row of depth_weights * bce
__device__ int   g_ps[MAXB];       // max streak of the row
__device__ unsigned int g_count = 0;

// Combine left (ap,as,ab | len la) with right (bp,bs,bb | len lb); result in a*.
#define SEG_COMBINE(ap, as, ab, la, bp, bs, bb, lb)              \
    do {                                                         \
        int _np = ((ap) == (la)) ? (la) + (bp) : (ap);           \
        int _ns = ((bs) == (lb)) ? (lb) + (as) : (bs);           \
        int _nb = max(max((ab), (bb)), (as) + (bp));             \
        (ap) = _np; (as) = _ns; (ab) = _nb;                      \
    } while (0)

// One CTA per row, 512 threads (16 warps). Warp w owns float4 [w*64, (w+1)*64).
// Lane i loads float4s (w*64 + 2i, 2i+1): 8 contiguous elements per thread,
// whole row covered in ONE pass -> single warp tree per thread, all 6 LDG.128
// front-batched for maximum MLP.
__global__ __launch_bounds__(512, 3)
void depth_loss_fused_kernel(const float4* __restrict__ p4,
                             const float4* __restrict__ t4,
                             const float4* __restrict__ w4,
                             float* __restrict__ out, int B)
{
    const int row  = blockIdx.x;
    const int tid  = threadIdx.x;
    const int warp = tid >> 5;
    const int lane = tid & 31;
    const size_t base = (size_t)row * (NCOLS / 4) + warp * 64 + lane * 2;

    // front-batch all loads (6 x LDG.128 in flight)
    float4 pA = __ldcs(&p4[base]), pB = __ldcs(&p4[base + 1]);
    float4 tA = __ldcs(&t4[base]), tB = __ldcs(&t4[base + 1]);
    float4 wA = __ldcs(&w4[base]), wB = __ldcs(&w4[base + 1]);

    float pp[8] = {pA.x, pA.y, pA.z, pA.w, pB.x, pB.y, pB.z, pB.w};
    float tt[8] = {tA.x, tA.y, tA.z, tA.w, tB.x, tB.y, tB.z, tB.w};
    float ww[8] = {wA.x, wA.y, wA.z, wA.w, wB.x, wB.y, wB.z, wB.w};

    // leaf state over this thread's 8 contiguous elements (branch-free)
    float wsum = 0.0f;
    int cur = 0, best = 0, pref = 0, all = 1;
#pragma unroll
    for (int e = 0; e < 8; e++) {
        bool tb = (tt[e] > 0.5f);
        bool pb = (pp[e] > 0.5f);
        int corr = (tb == pb) ? 1 : 0;
        float v = tb ? (pp[e] + EPS) : ((1.0f - pp[e]) + EPS);
        wsum = fmaf(ww[e], -__logf(v), wsum);
        cur  = corr ? (cur + 1) : 0;
        best = max(best, cur);
        all &= corr;
        pref += all;
    }
    int suf = cur;

    // warp tree: 8-elem leaves -> 256-elem warp segment (valid in lane 0);
    // fold the wsum reduction into the same shuffle levels.
#pragma unroll
    for (int s = 0; s < 5; s++) {
        int len = 8 << s;
        int op = __shfl_down_sync(0xffffffffu, pref, 1 << s);
        int os = __shfl_down_sync(0xffffffffu, suf,  1 << s);
        int ob = __shfl_down_sync(0xffffffffu, best, 1 << s);
        wsum  += __shfl_down_sync(0xffffffffu, wsum, 1 << s);
        SEG_COMBINE(pref, suf, best, len, op, os, ob, len);
    }

    __shared__ int   shp[16], shs[16], shb[16];
    __shared__ float shw[16];
    __shared__ int   s_isLast;
    if (lane == 0) { shp[warp] = pref; shs[warp] = suf; shb[warp] = best; shw[warp] = wsum; }
    __syncthreads();

    if (tid == 0) {
        int ap = shp[0], as = shs[0], ab = shb[0];
        float ws = shw[0];
#pragma unroll
        for (int wi = 1; wi < 16; wi++) {
            SEG_COMBINE(ap, as, ab, 256 * wi, shp[wi], shs[wi], shb[wi], 256);
            ws += shw[wi];
        }
        g_pw[row] = ws;
        g_ps[row] = ab;
        __threadfence();
        unsigned int done = atomicAdd(&g_count, 1u);
        s_isLast = (done == (unsigned int)(gridDim.x - 1)) ? 1 : 0;
    }
    __syncthreads();

    if (s_isLast) {
        __threadfence();   // acquire: see all rows' partials
        double dw = 0.0;
        long long dsi = 0;
        for (int r = tid; r < B; r += 2048) {
            float  a0 = g_pw[r], a1 = g_pw[r + 512], a2 = g_pw[r + 1024], a3 = g_pw[r + 1536];
            int    b0 = g_ps[r], b1 = g_ps[r + 512], b2 = g_ps[r + 1024], b3 = g_ps[r + 1536];
            dw  += (double)a0 + (double)a1 + (double)a2 + (double)a3;
            dsi += (long long)b0 + b1 + b2 + b3;
        }
        __shared__ double    rdw[512];
        __shared__ long long rds[512];
        rdw[tid] = dw;
        rds[tid] = dsi;
        __syncthreads();
#pragma unroll
        for (int st = 256; st > 0; st >>= 1) {
            if (tid < st) { rdw[tid] += rdw[tid + st]; rds[tid] += rds[tid + st]; }
            __syncthreads();
        }
        if (tid == 0) {
            double BN   = (double)B * (double)NCOLS;
            double wbce = rdw[0] / BN;                       // mean(w * bce)
            double cwl  = 1.0 - ((double)rds[0]) / BN;       // mean(1 - streak/N)
            out[0] = (float)(0.5 * wbce + 0.5 * cwl);
            g_count = 0;                                     // reset for next replay
        }
    }
}

extern "C" void kernel_launch(void* const* d_in, const int* in_sizes, int n_in,
                              void* d_out, int out_size)
{
    const float4* p4 = (const float4*)d_in[0];   // y_pred
    const float4* t4 = (const float4*)d_in[1];   // y_true
    const float4* w4 = (const float4*)d_in[2];   // depth_weights
    int total = in_sizes[0];
    int B = total / NCOLS;                       // 8192

    depth_loss_fused_kernel<<<B, 512>>>(p4, t4, w4, (float*)d_out, B);
}

// round 8
// speedup vs baseline: 1.0664x; 1.0664x over previous
#include <cuda_runtime.h>
#include <cuda_bf16.h>

#define EPS   1e-6f
#define NCOLS 4096
#define MAXB  8192
#define NBLK  444          // 148 SMs x 3 resident CTAs (persistent grid)

// Per-row streaks, per-CTA bce partials, completion counter (graph-replay safe).
__device__ int   g_ps[MAXB];       // max streak per row
__device__ float g_pw[NBLK];       // per-CTA sum of depth_weights * bce
__device__ unsigned int g_count = 0;

// Combine left (ap,as,ab | len la) with right (bp,bs,bb | len lb); result in a*.
#define SEG_COMBINE(ap, as, ab, la, bp, bs, bb, lb)              \
    do {                                                         \
        int _np = ((ap) == (la)) ? (la) + (bp) : (ap);           \
        int _ns = ((bs) == (lb)) ? (lb) + (as) : (bs);           \
        int _nb = max(max((ab), (bb)), (as) + (bp));             \
        (ap) = _np; (as) = _ns; (ab) = _nb;                      \
    } while (0)

// Persistent CTAs: 512 threads (16 warps), each CTA strides over rows.
// Warp w owns float4 [w*64, (w+1)*64); lane i loads float4s (2i, 2i+1):
// 8 contiguous elements/thread, one warp tree per row.
__global__ __launch_bounds__(512, 3)
void depth_loss_fused_kernel(const float4* __restrict__ p4,
                             const float4* __restrict__ t4,
                             const float4* __restrict__ w4,
                             float* __restrict__ out, int B)
{
    const int tid  = threadIdx.x;
    const int warp = tid >> 5;
    const int lane = tid & 31;

    __shared__ int shp[2][16], shs[2][16], shb[2][16];   // parity double-buffer
    __shared__ int s_isLast;

    float wacc = 0.0f;            // per-thread bce partial across all its rows
    int par = 0;

    for (int row = blockIdx.x; row < B; row += gridDim.x, par ^= 1) {
        const size_t base = (size_t)row * (NCOLS / 4) + warp * 64 + lane * 2;

        // front-batch all 6 LDG.128
        float4 pA = __ldcs(&p4[base]), pB = __ldcs(&p4[base + 1]);
        float4 tA = __ldcs(&t4[base]), tB = __ldcs(&t4[base + 1]);
        float4 wA = __ldcs(&w4[base]), wB = __ldcs(&w4[base + 1]);

        float pp[8] = {pA.x, pA.y, pA.z, pA.w, pB.x, pB.y, pB.z, pB.w};
        float tt[8] = {tA.x, tA.y, tA.z, tA.w, tB.x, tB.y, tB.z, tB.w};
        float ww[8] = {wA.x, wA.y, wA.z, wA.w, wB.x, wB.y, wB.z, wB.w};

        // leaf state over 8 contiguous elements (branch-free); bce into wacc
        int cur = 0, best = 0, pref = 0, all = 1;
#pragma unroll
        for (int e = 0; e < 8; e++) {
            bool tb = (tt[e] > 0.5f);
            bool pb = (pp[e] > 0.5f);
            int corr = (tb == pb) ? 1 : 0;
            float v = tb ? (pp[e] + EPS) : ((1.0f - pp[e]) + EPS);
            wacc = fmaf(ww[e], -__logf(v), wacc);
            cur  = corr ? (cur + 1) : 0;
            best = max(best, cur);
            all &= corr;
            pref += all;
        }
        int suf = cur;

        // warp tree: 8-elem leaves -> 256-elem warp segment (valid in lane 0)
#pragma unroll
        for (int s = 0; s < 5; s++) {
            int len = 8 << s;
            int op = __shfl_down_sync(0xffffffffu, pref, 1 << s);
            int os = __shfl_down_sync(0xffffffffu, suf,  1 << s);
            int ob = __shfl_down_sync(0xffffffffu, best, 1 << s);
            SEG_COMBINE(pref, suf, best, len, op, os, ob, len);
        }

        if (lane == 0) { shp[par][warp] = pref; shs[par][warp] = suf; shb[par][warp] = best; }
        __syncthreads();

        // tid0 combines this row while the other warps proceed to the next
        // row's loads (parity buffer slot [par] is not rewritten until
        // iteration row+2, which is fenced by iteration row+1's barrier).
        if (tid == 0) {
            int ap = shp[par][0], as = shs[par][0], ab = shb[par][0];
#pragma unroll
            for (int wi = 1; wi < 16; wi++)
                SEG_COMBINE(ap, as, ab, 256 * wi, shp[par][wi], shs[par][wi], shb[par][wi], 256);
            g_ps[row] = ab;                     // plain STG; released by CTA-end fence
        }
    }

    // ---- CTA end: reduce per-thread bce partials, one fence+atomic per CTA ----
#pragma unroll
    for (int s = 16; s > 0; s >>= 1)
        wacc += __shfl_down_sync(0xffffffffu, wacc, s);
    __shared__ float shwf[16];
    if (lane == 0) shwf[warp] = wacc;
    __syncthreads();
    if (tid == 0) {
        float ws = shwf[0];
#pragma unroll
        for (int wi = 1; wi < 16; wi++) ws += shwf[wi];
        g_pw[blockIdx.x] = ws;
        __threadfence();                         // release partials + streaks
        unsigned int done = atomicAdd(&g_count, 1u);
        s_isLast = (done == (unsigned int)(gridDim.x - 1)) ? 1 : 0;
    }
    __syncthreads();

    // ---- last CTA: final deterministic reduction ----
    if (s_isLast) {
        __threadfence();   // acquire: see all CTAs' partials
        double dw = 0.0;
        long long dsi = 0;
        for (int i = tid; i < (int)gridDim.x; i += 512)
            dw += (double)g_pw[i];
        for (int r = tid; r < B; r += 2048) {
            int b0 = g_ps[r], b1 = g_ps[r + 512], b2 = g_ps[r + 1024], b3 = g_ps[r + 1536];
            dsi += (long long)b0 + b1 + b2 + b3;
        }
        __shared__ double    rdw[512];
        __shared__ long long rds[512];
        rdw[tid] = dw;
        rds[tid] = dsi;
        __syncthreads();
#pragma unroll
        for (int st = 256; st > 0; st >>= 1) {
            if (tid < st) { rdw[tid] += rdw[tid + st]; rds[tid] += rds[tid + st]; }
            __syncthreads();
        }
        if (tid == 0) {
            double BN   = (double)B * (double)NCOLS;
            double wbce = rdw[0] / BN;                       // mean(w * bce)
            double cwl  = 1.0 - ((double)rds[0]) / BN;       // mean(1 - streak/N)
            out[0] = (float)(0.5 * wbce + 0.5 * cwl);
            g_count = 0;                                     // reset for next replay
        }
    }
}

extern "C" void kernel_launch(void* const* d_in, const int* in_sizes, int n_in,
                              void* d_out, int out_size)
{
    const float4* p4 = (const float4*)d_in[0];   // y_pred
    const float4* t4 = (const float4*)d_in[1];   // y_true
    const float4* w4 = (const float4*)d_in[2];   // depth_weights
    int total = in_sizes[0];
    int B = total / NCOLS;                       // 8192

    depth_loss_fused_kernel<<<NBLK, 512>>>(p4, t4, w4, (float*)d_out, B);
}